// round 4
// baseline (speedup 1.0000x reference)
#include <cuda_runtime.h>
#include <math.h>

#define NB 16
#define NC 33
#define HIN 256
#define WIN 256
#define HF 128
#define WF 128
#define NFLOW 10
#define NPIX (HF * WF)                 // 16384
#define TPB 256
#define TILES 8
#define PIX_PER_BLOCK (NPIX / TILES)   // 2048
#define WARP_BLOCKS (NB * NFLOW * TILES) // 1280
#define SMOOTH_ELEMS (NB * NFLOW * HF * WF) // 2,621,440
#define NCH (NB * NFLOW * 3)           // 480
#define RES_TOTAL (NB * NC * HF * WF)  // 8,650,752
#define PSTRIDE 18                     // per-block partials: 15 moments + pix + smooth + pad

// Scratch (device globals: allocation-free)
__device__ float g_resized[RES_TOTAL];               // ~34.6 MB
__device__ float g_part[WARP_BLOCKS * PSTRIDE];
__device__ int   g_ctr;                              // zero-initialized

// ---------------------------------------------------------------------------
// Kernel 1: align-corners bilinear resize 256x256 -> 128x128, all 33 channels
// ---------------------------------------------------------------------------
__global__ __launch_bounds__(TPB) void resize_kernel(const float* __restrict__ img) {
    int idx = blockIdx.x * TPB + threadIdx.x;
    int x  = idx & (WF - 1);
    int y  = (idx >> 7) & (HF - 1);
    int bc = idx >> 14;

    const float s = (float)(255.0 / 127.0);
    float fy = (float)y * s;
    float fx = (float)x * s;
    int y0 = min(max((int)floorf(fy), 0), HIN - 2);
    int x0 = min(max((int)floorf(fx), 0), WIN - 2);
    float wy = fy - (float)y0;
    float wx = fx - (float)x0;

    const float* p = img + (size_t)bc * (HIN * WIN);
    float v00 = __ldg(p + y0 * WIN + x0);
    float v01 = __ldg(p + y0 * WIN + x0 + 1);
    float v10 = __ldg(p + (y0 + 1) * WIN + x0);
    float v11 = __ldg(p + (y0 + 1) * WIN + x0 + 1);

    float colL = v00 * (1.0f - wy) + v10 * wy;
    float colR = v01 * (1.0f - wy) + v11 * wy;
    g_resized[idx] = colL * (1.0f - wx) + colR * wx;
}

__device__ __forceinline__ float charb(float d) {
    // (d^2 + EPS^2)^0.4, EPS = 1e-3
    return __powf(d * d + 1.0e-6f, 0.4f);
}

// ---------------------------------------------------------------------------
// Kernel 2 (MEGA): warp + SSIM moments + pixel charb + fused smoothness;
// last block to finish performs the finalization (threadFenceReduction).
// ---------------------------------------------------------------------------
__global__ __launch_bounds__(TPB) void warp_kernel(const float* __restrict__ flows,
                                                   float* __restrict__ out) {
    int bidx = blockIdx.x;
    int tile = bidx & (TILES - 1);
    int bf   = bidx >> 3;            // TILES == 8
    int b = bf / NFLOW;
    int f = bf % NFLOW;
    int tid = threadIdx.x;

    const float* fb  = flows + (size_t)b * 20 * NPIX;
    const float* fxp = fb + (size_t)(2 * f) * NPIX;
    const float* fyp = fxp + NPIX;
    const float* srcbase = g_resized + (size_t)(b * NC + 3 + f * 3) * NPIX;
    const float* refbase = g_resized + (size_t)(b * NC + f * 3) * NPIX;

    float acc[17];
#pragma unroll
    for (int i = 0; i < 17; i++) acc[i] = 0.0f;

    int p0 = tile * PIX_PER_BLOCK;
#pragma unroll
    for (int k = 0; k < PIX_PER_BLOCK; k += TPB) {
        int p = p0 + k + tid;
        int x = p & (WF - 1);
        int y = p >> 7;

        float flx = __ldg(fxp + p);
        float fly = __ldg(fyp + p);

        // ---- warp + SSIM moments + pixel charb ----
        float gx = (float)x + flx;
        float gy = (float)y + fly;
        float x0f = floorf(gx);
        float y0f = floorf(gy);
        float wx = gx - x0f;
        float wy = gy - y0f;
        int ix0 = min(max((int)x0f, 0), WF - 1);
        int iy0 = min(max((int)y0f, 0), HF - 1);
        int ix1 = min(ix0 + 1, WF - 1);
        int iy1 = min(iy0 + 1, HF - 1);

        int o00 = iy0 * WF + ix0;
        int o01 = iy0 * WF + ix1;
        int o10 = iy1 * WF + ix0;
        int o11 = iy1 * WF + ix1;

#pragma unroll
        for (int c = 0; c < 3; c++) {
            const float* sp = srcbase + c * NPIX;
            float v00 = __ldg(sp + o00);
            float v01 = __ldg(sp + o01);
            float v10 = __ldg(sp + o10);
            float v11 = __ldg(sp + o11);
            float top = v00 * (1.0f - wx) + v01 * wx;
            float bot = v10 * (1.0f - wx) + v11 * wx;
            float w   = top * (1.0f - wy) + bot * wy;
            float r   = __ldg(refbase + c * NPIX + p);

            acc[c * 5 + 0] += r;
            acc[c * 5 + 1] += w;
            acc[c * 5 + 2] += r * r;
            acc[c * 5 + 3] += w * w;
            acc[c * 5 + 4] += r * w;
            acc[15] += charb(r - w);
        }

        // ---- fused smoothness for flow pair f at this pixel ----
        int px = y * WF + x;
#pragma unroll
        for (int comp = 0; comp < 2; comp++) {
            const float* ch = fb + (2 * f + comp) * NPIX;
            float center = (comp == 0) ? flx : fly;
            // gradient along flow-index axis (channel stride 2)
            float gi;
            if (f == 0)
                gi = __ldg(fb + (2 + comp) * NPIX + px) - center;
            else if (f == NFLOW - 1)
                gi = center - __ldg(fb + (2 * (NFLOW - 2) + comp) * NPIX + px);
            else
                gi = 0.5f * (__ldg(fb + (2 * (f + 1) + comp) * NPIX + px) -
                             __ldg(fb + (2 * (f - 1) + comp) * NPIX + px));
            // gradient along H
            float gh;
            if (y == 0)
                gh = __ldg(ch + WF + x) - center;
            else if (y == HF - 1)
                gh = center - __ldg(ch + (HF - 2) * WF + x);
            else
                gh = 0.5f * (__ldg(ch + (y + 1) * WF + x) - __ldg(ch + (y - 1) * WF + x));

            acc[16] += charb(gi) + charb(gh);
        }
    }

    // Deterministic block reduction: warp shuffles, 8-warp combine.
    __shared__ float sm[8 * 17];
    int lane = tid & 31;
    int wrp  = tid >> 5;
#pragma unroll
    for (int i = 0; i < 17; i++) {
        float v = acc[i];
#pragma unroll
        for (int o = 16; o > 0; o >>= 1) v += __shfl_down_sync(0xffffffffu, v, o);
        if (lane == 0) sm[wrp * 17 + i] = v;
    }
    __syncthreads();
    if (tid < 17) {
        float s = 0.0f;
#pragma unroll
        for (int w = 0; w < 8; w++) s += sm[w * 17 + tid];
        g_part[bidx * PSTRIDE + tid] = s;
    }

    // ---- last-block finalization ----
    __shared__ bool is_last;
    __threadfence();
    __syncthreads();
    if (tid == 0) {
        int old = atomicAdd(&g_ctr, 1);
        is_last = (old == WARP_BLOCKS - 1);
    }
    __syncthreads();
    if (!is_last) return;
    __threadfence();

    __shared__ float smom[NCH * 5];   // 2400 floats
    // Per-(channel,moment) sums over 8 tile partials.
    for (int t = tid; t < NCH * 5; t += TPB) {
        int bfc = t / 5;
        int m   = t % 5;
        int bfi = bfc / 3;
        int c   = bfc % 3;
        const float* p = g_part + (size_t)(bfi * TILES) * PSTRIDE + c * 5 + m;
        float s = 0.0f;
#pragma unroll
        for (int tl = 0; tl < TILES; tl++) s += p[tl * PSTRIDE];
        smom[t] = s;
    }

    float pix_s = 0.0f, sm_s = 0.0f;
    for (int i = tid; i < WARP_BLOCKS; i += TPB) {
        pix_s += g_part[i * PSTRIDE + 15];
        sm_s  += g_part[i * PSTRIDE + 16];
    }
    __syncthreads();

    // Per-channel SSIM in f32.
    float ssim_s = 0.0f;
    for (int ch = tid; ch < NCH; ch += TPB) {
        const float* m = smom + ch * 5;
        float S1 = m[0], S2 = m[1], S11 = m[2], S22 = m[3], S12 = m[4];
        const float invN   = 1.0f / (float)NPIX;
        const float invNm1 = 1.0f / (float)(NPIX - 1);
        float mu1 = S1 * invN, mu2 = S2 * invN;
        float var1 = (S11 - S1 * S1 * invN) * invNm1;
        float var2 = (S22 - S2 * S2 * invN) * invNm1;
        float s12  = (S12 - S1 * S2 * invN) * invN;
        float num = (2.0f * mu1 * mu2 + 1.0e-4f) * (2.0f * s12 + 1.0e-3f);
        float den = (mu1 * mu1 + mu2 * mu2 + 1.0e-4f) * (var1 + var2 + 1.0e-3f);
        ssim_s += num / den;
    }

    // Fused triple reduction (8 warps).
    __shared__ float sred[3 * 8];
#pragma unroll
    for (int o = 16; o > 0; o >>= 1) {
        ssim_s += __shfl_down_sync(0xffffffffu, ssim_s, o);
        pix_s  += __shfl_down_sync(0xffffffffu, pix_s,  o);
        sm_s   += __shfl_down_sync(0xffffffffu, sm_s,   o);
    }
    if (lane == 0) {
        sred[wrp * 3 + 0] = ssim_s;
        sred[wrp * 3 + 1] = pix_s;
        sred[wrp * 3 + 2] = sm_s;
    }
    __syncthreads();
    if (tid == 0) {
        float a = 0.0f, bb = 0.0f, cc = 0.0f;
#pragma unroll
        for (int w = 0; w < 8; w++) {
            a  += sred[w * 3 + 0];
            bb += sred[w * 3 + 1];
            cc += sred[w * 3 + 2];
        }
        out[0] = bb * (1.0f / (float)(NB * NFLOW * 3 * NPIX))   // pixel (w=1.0)
               + 0.01f * cc * (1.0f / (float)SMOOTH_ELEMS)      // smooth (w=0.01)
               + a * (1.0f / (float)NCH);                       // ssim (w=1.0)
        g_ctr = 0;  // reset for next graph replay
    }
}

extern "C" void kernel_launch(void* const* d_in, const int* in_sizes, int n_in,
                              void* d_out, int out_size) {
    const float* images = (const float*)d_in[0];  // (16,33,256,256) f32
    const float* flows  = (const float*)d_in[1];  // (16,20,128,128) f32
    (void)in_sizes; (void)n_in; (void)out_size;

    resize_kernel<<<RES_TOTAL / TPB, TPB>>>(images);
    warp_kernel<<<WARP_BLOCKS, TPB>>>(flows, (float*)d_out);
}

// round 5
// speedup vs baseline: 1.0941x; 1.0941x over previous
#include <cuda_runtime.h>
#include <math.h>

#define NB 16
#define NC 33
#define HIN 256
#define WIN 256
#define HF 128
#define WF 128
#define NFLOW 10
#define NPIX (HF * WF)                 // 16384
#define TPB 256
#define TILES 8
#define PIX_PER_BLOCK (NPIX / TILES)   // 2048
#define WARP_BLOCKS (NB * NFLOW * TILES) // 1280
#define SMOOTH_ELEMS (NB * NFLOW * HF * WF) // 2,621,440
#define SMOOTH_BLOCKS 2560             // 2560 * 1024 = SMOOTH_ELEMS
#define NCH (NB * NFLOW * 3)           // 480
#define RES_TOTAL (NB * NC * HF * WF)  // 8,650,752
#define RES_BLOCKS (RES_TOTAL / TPB)   // 33792

// Scratch (device globals: allocation-free)
__device__ float g_resized[RES_TOTAL];             // ~34.6 MB
__device__ float g_warp_part[WARP_BLOCKS * 16];    // 3ch x 5 moments + pixel charb
__device__ float g_smooth_part[SMOOTH_BLOCKS];
__device__ int   g_ctr;                            // zero-initialized

__device__ __forceinline__ float charb(float d) {
    // (d^2 + EPS^2)^0.4, EPS = 1e-3
    return __powf(d * d + 1.0e-6f, 0.4f);
}

// ---------------------------------------------------------------------------
// Kernel A: smooth blocks first (L2/MUFU-bound), then resize blocks
// (DRAM-bound) — independent work, overlapped in one launch.
// ---------------------------------------------------------------------------
__global__ __launch_bounds__(TPB) void resize_smooth_kernel(
        const float* __restrict__ img, const float* __restrict__ flows) {

    if (blockIdx.x < SMOOTH_BLOCKS) {
        // ---------------- smoothness ----------------
        int base = blockIdx.x * (TPB * 4);
        float acc = 0.0f;
#pragma unroll
        for (int k = 0; k < 4; k++) {
            int e = base + k * TPB + threadIdx.x;
            int x  = e & (WF - 1);
            int y  = (e >> 7) & (HF - 1);
            int bi = e >> 14;
            int i  = bi % NFLOW;
            int b  = bi / NFLOW;
            const float* fb = flows + (size_t)b * 20 * NPIX;
            int px = y * WF + x;

#pragma unroll
            for (int comp = 0; comp < 2; comp++) {
                const float* ch = fb + (2 * i + comp) * NPIX;
                float gi;
                if (i == 0)
                    gi = __ldg(fb + (2 + comp) * NPIX + px) - __ldg(ch + px);
                else if (i == NFLOW - 1)
                    gi = __ldg(ch + px) - __ldg(fb + (2 * (NFLOW - 2) + comp) * NPIX + px);
                else
                    gi = 0.5f * (__ldg(fb + (2 * (i + 1) + comp) * NPIX + px) -
                                 __ldg(fb + (2 * (i - 1) + comp) * NPIX + px));
                float gh;
                if (y == 0)
                    gh = __ldg(ch + WF + x) - __ldg(ch + px);
                else if (y == HF - 1)
                    gh = __ldg(ch + px) - __ldg(ch + (HF - 2) * WF + x);
                else
                    gh = 0.5f * (__ldg(ch + (y + 1) * WF + x) - __ldg(ch + (y - 1) * WF + x));

                acc += charb(gi) + charb(gh);
            }
        }

        __shared__ float sm[8];
        int lane = threadIdx.x & 31;
        int wrp  = threadIdx.x >> 5;
#pragma unroll
        for (int o = 16; o > 0; o >>= 1) acc += __shfl_down_sync(0xffffffffu, acc, o);
        if (lane == 0) sm[wrp] = acc;
        __syncthreads();
        if (threadIdx.x == 0) {
            float s = 0.0f;
#pragma unroll
            for (int w = 0; w < 8; w++) s += sm[w];
            g_smooth_part[blockIdx.x] = s;
        }
    } else {
        // ---------------- resize (align-corners bilinear 256->128) ----------------
        int idx = (blockIdx.x - SMOOTH_BLOCKS) * TPB + threadIdx.x;
        int x  = idx & (WF - 1);
        int y  = (idx >> 7) & (HF - 1);
        int bc = idx >> 14;

        const float s = (float)(255.0 / 127.0);
        float fy = (float)y * s;
        float fx = (float)x * s;
        int y0 = min(max((int)floorf(fy), 0), HIN - 2);
        int x0 = min(max((int)floorf(fx), 0), WIN - 2);
        float wy = fy - (float)y0;
        float wx = fx - (float)x0;

        const float* p = img + (size_t)bc * (HIN * WIN);
        float v00 = __ldg(p + y0 * WIN + x0);
        float v01 = __ldg(p + y0 * WIN + x0 + 1);
        float v10 = __ldg(p + (y0 + 1) * WIN + x0);
        float v11 = __ldg(p + (y0 + 1) * WIN + x0 + 1);

        float colL = v00 * (1.0f - wy) + v10 * wy;
        float colR = v01 * (1.0f - wy) + v11 * wy;
        g_resized[idx] = colL * (1.0f - wx) + colR * wx;
    }
}

// ---------------------------------------------------------------------------
// Kernel B: bilinear warp + SSIM moments + pixel charbonnier (R3's lean loop);
// last block to finish performs the full finalization.
// ---------------------------------------------------------------------------
__global__ __launch_bounds__(TPB) void warp_kernel(const float* __restrict__ flows,
                                                   float* __restrict__ out) {
    int bidx = blockIdx.x;
    int tile = bidx & (TILES - 1);
    int bf   = bidx >> 3;            // TILES == 8
    int b = bf / NFLOW;
    int f = bf % NFLOW;
    int tid = threadIdx.x;

    const float* fxp = flows + (size_t)(b * 20 + 2 * f) * NPIX;
    const float* fyp = fxp + NPIX;
    const float* srcbase = g_resized + (size_t)(b * NC + 3 + f * 3) * NPIX;
    const float* refbase = g_resized + (size_t)(b * NC + f * 3) * NPIX;

    float acc[16];
#pragma unroll
    for (int i = 0; i < 16; i++) acc[i] = 0.0f;

    int p0 = tile * PIX_PER_BLOCK;
#pragma unroll
    for (int k = 0; k < PIX_PER_BLOCK; k += TPB) {
        int p = p0 + k + tid;
        int x = p & (WF - 1);
        int y = p >> 7;

        float gx = (float)x + __ldg(fxp + p);
        float gy = (float)y + __ldg(fyp + p);
        float x0f = floorf(gx);
        float y0f = floorf(gy);
        float wx = gx - x0f;
        float wy = gy - y0f;
        int ix0 = min(max((int)x0f, 0), WF - 1);
        int iy0 = min(max((int)y0f, 0), HF - 1);
        int ix1 = min(ix0 + 1, WF - 1);
        int iy1 = min(iy0 + 1, HF - 1);

        int o00 = iy0 * WF + ix0;
        int o01 = iy0 * WF + ix1;
        int o10 = iy1 * WF + ix0;
        int o11 = iy1 * WF + ix1;

#pragma unroll
        for (int c = 0; c < 3; c++) {
            const float* sp = srcbase + c * NPIX;
            float v00 = __ldg(sp + o00);
            float v01 = __ldg(sp + o01);
            float v10 = __ldg(sp + o10);
            float v11 = __ldg(sp + o11);
            float top = v00 * (1.0f - wx) + v01 * wx;
            float bot = v10 * (1.0f - wx) + v11 * wx;
            float w   = top * (1.0f - wy) + bot * wy;
            float r   = __ldg(refbase + c * NPIX + p);

            acc[c * 5 + 0] += r;
            acc[c * 5 + 1] += w;
            acc[c * 5 + 2] += r * r;
            acc[c * 5 + 3] += w * w;
            acc[c * 5 + 4] += r * w;
            acc[15] += charb(r - w);
        }
    }

    __shared__ float sm[8 * 16];
    int lane = tid & 31;
    int wrp  = tid >> 5;
#pragma unroll
    for (int i = 0; i < 16; i++) {
        float v = acc[i];
#pragma unroll
        for (int o = 16; o > 0; o >>= 1) v += __shfl_down_sync(0xffffffffu, v, o);
        if (lane == 0) sm[wrp * 16 + i] = v;
    }
    __syncthreads();
    if (tid < 16) {
        float s = 0.0f;
#pragma unroll
        for (int w = 0; w < 8; w++) s += sm[w * 16 + tid];
        g_warp_part[bidx * 16 + tid] = s;
    }

    // ---- last-block finalization ----
    __shared__ bool is_last;
    __threadfence();
    __syncthreads();
    if (tid == 0) {
        int old = atomicAdd(&g_ctr, 1);
        is_last = (old == WARP_BLOCKS - 1);
    }
    __syncthreads();
    if (!is_last) return;
    __threadfence();

    __shared__ float smom[NCH * 5];   // 2400 floats
    for (int t = tid; t < NCH * 5; t += TPB) {
        int bfc = t / 5;
        int m   = t % 5;
        int bfi = bfc / 3;
        int c   = bfc % 3;
        const float* pp = g_warp_part + (size_t)(bfi * TILES) * 16 + c * 5 + m;
        float s = 0.0f;
#pragma unroll
        for (int tl = 0; tl < TILES; tl++) s += pp[tl * 16];
        smom[t] = s;
    }

    float pix_s = 0.0f, sm_s = 0.0f;
    for (int i = tid; i < WARP_BLOCKS; i += TPB)
        pix_s += g_warp_part[i * 16 + 15];
    for (int i = tid; i < SMOOTH_BLOCKS; i += TPB)
        sm_s += g_smooth_part[i];
    __syncthreads();

    float ssim_s = 0.0f;
    for (int ch = tid; ch < NCH; ch += TPB) {
        const float* m = smom + ch * 5;
        float S1 = m[0], S2 = m[1], S11 = m[2], S22 = m[3], S12 = m[4];
        const float invN   = 1.0f / (float)NPIX;
        const float invNm1 = 1.0f / (float)(NPIX - 1);
        float mu1 = S1 * invN, mu2 = S2 * invN;
        float var1 = (S11 - S1 * S1 * invN) * invNm1;
        float var2 = (S22 - S2 * S2 * invN) * invNm1;
        float s12  = (S12 - S1 * S2 * invN) * invN;
        float num = (2.0f * mu1 * mu2 + 1.0e-4f) * (2.0f * s12 + 1.0e-3f);
        float den = (mu1 * mu1 + mu2 * mu2 + 1.0e-4f) * (var1 + var2 + 1.0e-3f);
        ssim_s += num / den;
    }

    __shared__ float sred[3 * 8];
#pragma unroll
    for (int o = 16; o > 0; o >>= 1) {
        ssim_s += __shfl_down_sync(0xffffffffu, ssim_s, o);
        pix_s  += __shfl_down_sync(0xffffffffu, pix_s,  o);
        sm_s   += __shfl_down_sync(0xffffffffu, sm_s,   o);
    }
    if (lane == 0) {
        sred[wrp * 3 + 0] = ssim_s;
        sred[wrp * 3 + 1] = pix_s;
        sred[wrp * 3 + 2] = sm_s;
    }
    __syncthreads();
    if (tid == 0) {
        float a = 0.0f, bb = 0.0f, cc = 0.0f;
#pragma unroll
        for (int w = 0; w < 8; w++) {
            a  += sred[w * 3 + 0];
            bb += sred[w * 3 + 1];
            cc += sred[w * 3 + 2];
        }
        out[0] = bb * (1.0f / (float)(NB * NFLOW * 3 * NPIX))   // pixel (w=1.0)
               + 0.01f * cc * (1.0f / (float)SMOOTH_ELEMS)      // smooth (w=0.01)
               + a * (1.0f / (float)NCH);                       // ssim (w=1.0)
        g_ctr = 0;  // reset for next graph replay
    }
}

extern "C" void kernel_launch(void* const* d_in, const int* in_sizes, int n_in,
                              void* d_out, int out_size) {
    const float* images = (const float*)d_in[0];  // (16,33,256,256) f32
    const float* flows  = (const float*)d_in[1];  // (16,20,128,128) f32
    (void)in_sizes; (void)n_in; (void)out_size;

    resize_smooth_kernel<<<SMOOTH_BLOCKS + RES_BLOCKS, TPB>>>(images, flows);
    warp_kernel<<<WARP_BLOCKS, TPB>>>(flows, (float*)d_out);
}